// round 2
// baseline (speedup 1.0000x reference)
#include <cuda_runtime.h>
#include <cuda_bf16.h>

#define MAXN 100000
#define MAXE 1600000

// ---------------- scratch (static device globals; no allocation) ----------------
__device__ __align__(16) float g_t[MAXN * 128];   // post-GEMM features
__device__ __align__(16) float g_h[MAXN * 128];   // post-aggregation features
__device__ float g_dinv[MAXN];
__device__ float g_selfc[MAXN];
__device__ int   g_cnt[MAXN];
__device__ int   g_rowp[MAXN + 1];
__device__ int   g_cur[MAXN];
__device__ int   g_col[MAXE];
__device__ float g_w[MAXE];
__device__ float g_stats[256];   // [0:128) sum, [128:256) sumsq
__device__ float g_a[128];       // BN fused scale
__device__ float g_c2[128];      // BN fused shift
__device__ float g_sc[128];      // scene_context @ W1[64:128,:]

// ---------------- preprocessing ----------------
__global__ void k_zero(int n) {
    int i = blockIdx.x * blockDim.x + threadIdx.x;
    if (i < n) g_cnt[i] = 0;
    if (i < 256) g_stats[i] = 0.f;
}

__global__ void k_count(const int* __restrict__ dst, int E) {
    int e = blockIdx.x * blockDim.x + threadIdx.x;
    if (e < E) atomicAdd(&g_cnt[dst[e]], 1);
}

__global__ void k_deg(int n) {
    int i = blockIdx.x * blockDim.x + threadIdx.x;
    if (i < n) {
        float d = 1.f + (float)g_cnt[i];
        float r = rsqrtf(d);
        g_dinv[i] = r;
        g_selfc[i] = r * r;
    }
}

// single-block exclusive scan of g_cnt -> g_rowp (and cursor copy g_cur)
__global__ void k_scan(int n, int E) {
    __shared__ int ssum[1024];
    int t = threadIdx.x;
    int chunk = (n + 1023) >> 10;
    int beg = t * chunk;
    int end = min(beg + chunk, n);
    int s = 0;
    for (int i = beg; i < end; i++) s += g_cnt[i];
    ssum[t] = s;
    __syncthreads();
    for (int off = 1; off < 1024; off <<= 1) {
        int v = 0;
        if (t >= off) v = ssum[t - off];
        __syncthreads();
        ssum[t] += v;
        __syncthreads();
    }
    int run = ssum[t] - s;  // exclusive prefix
    for (int i = beg; i < end; i++) {
        g_rowp[i] = run;
        g_cur[i] = run;
        run += g_cnt[i];
    }
    if (t == 0) g_rowp[n] = E;
}

__global__ void k_scatter(const int* __restrict__ src, const int* __restrict__ dst, int E) {
    int e = blockIdx.x * blockDim.x + threadIdx.x;
    if (e < E) {
        int d = dst[e], s = src[e];
        int p = atomicAdd(&g_cur[d], 1);
        g_col[p] = s;
        g_w[p] = g_dinv[s] * g_dinv[d];
    }
}

// sc[c] = sum_j scene[j] * W1[64+j][c]   (constant row of layer-1 GEMM output)
__global__ void k_prep(const float* __restrict__ scene, const float* __restrict__ W1) {
    int c = threadIdx.x;
    float s = 0.f;
    for (int j = 0; j < 64; j++) s = fmaf(scene[j], W1[(64 + j) * 128 + c], s);
    g_sc[c] = s;
}

// ---------------- GEMM: C[n,128] = op(A[n,K]) @ B[K,128] (+ addrow) ----------------
// op = identity (TR=false) or fused BN+ReLU: relu(a*v + c) (TR=true)
template <int K, bool TR>
__global__ void __launch_bounds__(256) k_gemm(const float* __restrict__ A,
                                              const float* __restrict__ B,
                                              float* __restrict__ C,
                                              const float* __restrict__ addrow,
                                              int n) {
    extern __shared__ float smem[];
    float* Bs = smem;            // K*128
    float* As = smem + K * 128;  // K*64  (transposed: As[k*64 + r])
    int tid = threadIdx.x;
    int row0 = blockIdx.x * 64;

    for (int i = tid; i < K * 32; i += 256)
        ((float4*)Bs)[i] = ((const float4*)B)[i];

    for (int i = tid; i < 64 * (K / 4); i += 256) {
        int r = i / (K / 4);
        int kq = i - r * (K / 4);
        int grow = row0 + r;
        float4 v = make_float4(0.f, 0.f, 0.f, 0.f);
        if (grow < n) v = ((const float4*)A)[grow * (K / 4) + kq];
        int k = kq * 4;
        if (TR) {
            v.x = fmaxf(fmaf(v.x, g_a[k + 0], g_c2[k + 0]), 0.f);
            v.y = fmaxf(fmaf(v.y, g_a[k + 1], g_c2[k + 1]), 0.f);
            v.z = fmaxf(fmaf(v.z, g_a[k + 2], g_c2[k + 2]), 0.f);
            v.w = fmaxf(fmaf(v.w, g_a[k + 3], g_c2[k + 3]), 0.f);
        }
        As[(k + 0) * 64 + r] = v.x;
        As[(k + 1) * 64 + r] = v.y;
        As[(k + 2) * 64 + r] = v.z;
        As[(k + 3) * 64 + r] = v.w;
    }
    __syncthreads();

    int tr = tid >> 4;  // 0..15 -> rows tr*4 .. tr*4+3
    int tc = tid & 15;  // 0..15 -> cols tc*8 .. tc*8+7
    float acc[4][8];
#pragma unroll
    for (int r = 0; r < 4; r++)
#pragma unroll
        for (int c = 0; c < 8; c++) acc[r][c] = 0.f;

#pragma unroll 8
    for (int k = 0; k < K; k++) {
        float4 a = *(const float4*)(As + k * 64 + tr * 4);
        float4 b0 = *(const float4*)(Bs + k * 128 + tc * 8);
        float4 b1 = *(const float4*)(Bs + k * 128 + tc * 8 + 4);
        float av[4] = {a.x, a.y, a.z, a.w};
        float bv[8] = {b0.x, b0.y, b0.z, b0.w, b1.x, b1.y, b1.z, b1.w};
#pragma unroll
        for (int r = 0; r < 4; r++)
#pragma unroll
            for (int c = 0; c < 8; c++)
                acc[r][c] = fmaf(av[r], bv[c], acc[r][c]);
    }

    float add[8];
#pragma unroll
    for (int c = 0; c < 8; c++) add[c] = addrow ? addrow[tc * 8 + c] : 0.f;

#pragma unroll
    for (int r = 0; r < 4; r++) {
        int grow = row0 + tr * 4 + r;
        if (grow < n) {
            float4 o0 = make_float4(acc[r][0] + add[0], acc[r][1] + add[1],
                                    acc[r][2] + add[2], acc[r][3] + add[3]);
            float4 o1 = make_float4(acc[r][4] + add[4], acc[r][5] + add[5],
                                    acc[r][6] + add[6], acc[r][7] + add[7]);
            ((float4*)C)[grow * 32 + tc * 2] = o0;
            ((float4*)C)[grow * 32 + tc * 2 + 1] = o1;
        }
    }
}

// ---------------- aggregation: h[i] = relu(sum_e w*t[col] + selfc[i]*t[i] + b) ----------------
// warp per node, float4 per lane (4 channels). Fuses BN statistics accumulation.
__global__ void __launch_bounds__(256) k_agg(const float* __restrict__ t,
                                             float* __restrict__ h,
                                             const float* __restrict__ bias,
                                             int n) {
    __shared__ float bsum[128];
    __shared__ float bsq[128];
    int tid = threadIdx.x;
    if (tid < 128) { bsum[tid] = 0.f; bsq[tid] = 0.f; }
    __syncthreads();

    int lane = tid & 31;
    int gw = (blockIdx.x * 256 + tid) >> 5;
    int nw = (gridDim.x * 256) >> 5;
    const float4* t4 = (const float4*)t;
    float4 bi = ((const float4*)bias)[lane];
    float sx = 0, sy = 0, sz = 0, sw = 0;
    float qx = 0, qy = 0, qz = 0, qw = 0;

    for (int i = gw; i < n; i += nw) {
        int s = g_rowp[i], e = g_rowp[i + 1];
        float ax = 0, ay = 0, az = 0, aw = 0;
        int ee = s;
        for (; ee + 3 < e; ee += 4) {
            int j0 = g_col[ee], j1 = g_col[ee + 1], j2 = g_col[ee + 2], j3 = g_col[ee + 3];
            float w0 = g_w[ee], w1 = g_w[ee + 1], w2 = g_w[ee + 2], w3 = g_w[ee + 3];
            float4 v0 = t4[j0 * 32 + lane];
            float4 v1 = t4[j1 * 32 + lane];
            float4 v2 = t4[j2 * 32 + lane];
            float4 v3 = t4[j3 * 32 + lane];
            ax = fmaf(w0, v0.x, ax); ay = fmaf(w0, v0.y, ay); az = fmaf(w0, v0.z, az); aw = fmaf(w0, v0.w, aw);
            ax = fmaf(w1, v1.x, ax); ay = fmaf(w1, v1.y, ay); az = fmaf(w1, v1.z, az); aw = fmaf(w1, v1.w, aw);
            ax = fmaf(w2, v2.x, ax); ay = fmaf(w2, v2.y, ay); az = fmaf(w2, v2.z, az); aw = fmaf(w2, v2.w, aw);
            ax = fmaf(w3, v3.x, ax); ay = fmaf(w3, v3.y, ay); az = fmaf(w3, v3.z, az); aw = fmaf(w3, v3.w, aw);
        }
        for (; ee < e; ee++) {
            int j = g_col[ee];
            float w0 = g_w[ee];
            float4 v = t4[j * 32 + lane];
            ax = fmaf(w0, v.x, ax); ay = fmaf(w0, v.y, ay); az = fmaf(w0, v.z, az); aw = fmaf(w0, v.w, aw);
        }
        float sc = g_selfc[i];
        float4 vs = t4[i * 32 + lane];
        float rx = fmaxf(fmaf(sc, vs.x, ax) + bi.x, 0.f);
        float ry = fmaxf(fmaf(sc, vs.y, ay) + bi.y, 0.f);
        float rz = fmaxf(fmaf(sc, vs.z, az) + bi.z, 0.f);
        float rw = fmaxf(fmaf(sc, vs.w, aw) + bi.w, 0.f);
        float4 r = make_float4(rx, ry, rz, rw);
        ((float4*)h)[i * 32 + lane] = r;
        sx += rx; sy += ry; sz += rz; sw += rw;
        qx += rx * rx; qy += ry * ry; qz += rz * rz; qw += rw * rw;
    }

    int c = lane * 4;
    atomicAdd(&bsum[c + 0], sx); atomicAdd(&bsum[c + 1], sy);
    atomicAdd(&bsum[c + 2], sz); atomicAdd(&bsum[c + 3], sw);
    atomicAdd(&bsq[c + 0], qx); atomicAdd(&bsq[c + 1], qy);
    atomicAdd(&bsq[c + 2], qz); atomicAdd(&bsq[c + 3], qw);
    __syncthreads();
    if (tid < 128) {
        atomicAdd(&g_stats[tid], bsum[tid]);
        atomicAdd(&g_stats[128 + tid], bsq[tid]);
    }
}

// ---------------- BN finalize: a = g*rsqrt(var+eps), c2 = be - mu*a; reset stats ----------------
__global__ void k_bnfix(const float* __restrict__ gam, const float* __restrict__ bet, float invN) {
    int c = threadIdx.x;
    float mu = g_stats[c] * invN;
    float var = g_stats[128 + c] * invN - mu * mu;
    float a = gam[c] * rsqrtf(var + 1e-5f);
    g_a[c] = a;
    g_c2[c] = bet[c] - mu * a;
    g_stats[c] = 0.f;
    g_stats[128 + c] = 0.f;
}

// ---------------- output GEMM: out[n,8] = relu(bn(h)) @ Wout + bout ----------------
__global__ void __launch_bounds__(256) k_out(const float* __restrict__ h,
                                             const float* __restrict__ Wout,
                                             const float* __restrict__ bout,
                                             float* __restrict__ out,
                                             int n) {
    int tid = threadIdx.x;
    int lane = tid & 31;
    int gw = (blockIdx.x * 256 + tid) >> 5;
    int nw = (gridDim.x * 256) >> 5;
    const float4* h4 = (const float4*)h;
    int k = lane * 4;
    float a0 = g_a[k], a1 = g_a[k + 1], a2 = g_a[k + 2], a3 = g_a[k + 3];
    float c0 = g_c2[k], c1 = g_c2[k + 1], c2 = g_c2[k + 2], c3 = g_c2[k + 3];
    float wreg[4][8];
#pragma unroll
    for (int j = 0; j < 4; j++)
#pragma unroll
        for (int c = 0; c < 8; c++) wreg[j][c] = Wout[(k + j) * 8 + c];
    float b0 = bout[0], b1 = bout[1], b2 = bout[2], b3 = bout[3];
    float b4 = bout[4], b5 = bout[5], b6 = bout[6], b7 = bout[7];

    for (int i = gw; i < n; i += nw) {
        float4 v = h4[i * 32 + lane];
        float v0 = fmaxf(fmaf(v.x, a0, c0), 0.f);
        float v1 = fmaxf(fmaf(v.y, a1, c1), 0.f);
        float v2 = fmaxf(fmaf(v.z, a2, c2), 0.f);
        float v3 = fmaxf(fmaf(v.w, a3, c3), 0.f);
        float p[8];
#pragma unroll
        for (int c = 0; c < 8; c++) {
            p[c] = fmaf(v0, wreg[0][c],
                   fmaf(v1, wreg[1][c],
                   fmaf(v2, wreg[2][c], v3 * wreg[3][c])));
        }
#pragma unroll
        for (int c = 0; c < 8; c++) {
            p[c] += __shfl_down_sync(0xffffffffu, p[c], 16);
            p[c] += __shfl_down_sync(0xffffffffu, p[c], 8);
            p[c] += __shfl_down_sync(0xffffffffu, p[c], 4);
            p[c] += __shfl_down_sync(0xffffffffu, p[c], 2);
            p[c] += __shfl_down_sync(0xffffffffu, p[c], 1);
        }
        if (lane == 0) {
            float4 o0 = make_float4(p[0] + b0, p[1] + b1, p[2] + b2, p[3] + b3);
            float4 o1 = make_float4(p[4] + b4, p[5] + b5, p[6] + b6, p[7] + b7);
            ((float4*)out)[i * 2] = o0;
            ((float4*)out)[i * 2 + 1] = o1;
        }
    }
}

// ---------------- launch ----------------
extern "C" void kernel_launch(void* const* d_in, const int* in_sizes, int n_in,
                              void* d_out, int out_size) {
    const float* x     = (const float*)d_in[0];
    const int*   src   = (const int*)d_in[1];
    const int*   dst   = (const int*)d_in[2];
    const float* scene = (const float*)d_in[3];
    const float* W1    = (const float*)d_in[4];
    const float* b1    = (const float*)d_in[5];
    const float* g1    = (const float*)d_in[6];
    const float* be1   = (const float*)d_in[7];
    const float* W2    = (const float*)d_in[8];
    const float* b2    = (const float*)d_in[9];
    const float* g2    = (const float*)d_in[10];
    const float* be2   = (const float*)d_in[11];
    const float* Wout  = (const float*)d_in[12];
    const float* bout  = (const float*)d_in[13];
    float* out = (float*)d_out;

    int n = in_sizes[0] / 64;
    int E = in_sizes[1];

    float *pt, *ph, *psc;
    cudaGetSymbolAddress((void**)&pt, g_t);
    cudaGetSymbolAddress((void**)&ph, g_h);
    cudaGetSymbolAddress((void**)&psc, g_sc);

    cudaFuncSetAttribute(k_gemm<64, false>, cudaFuncAttributeMaxDynamicSharedMemorySize, 64 * 768);
    cudaFuncSetAttribute(k_gemm<128, true>, cudaFuncAttributeMaxDynamicSharedMemorySize, 128 * 768);

    int gbn = (n + 255) / 256;
    int gbe = (E + 255) / 256;
    int ggemm = (n + 63) / 64;
    int gagg = 2368;  // 148 SMs * 16 blocks: shrink tail quantization, raise MLP
    float invN = 1.0f / (float)n;

    // graph preprocessing (reused by both layers)
    k_zero<<<gbn, 256>>>(n);
    k_count<<<gbe, 256>>>(dst, E);
    k_deg<<<gbn, 256>>>(n);
    k_scan<<<1, 1024>>>(n, E);
    k_scatter<<<gbe, 256>>>(src, dst, E);
    k_prep<<<1, 128>>>(scene, W1);

    // layer 1
    k_gemm<64, false><<<ggemm, 256, 64 * 768>>>(x, W1, pt, psc, n);
    k_agg<<<gagg, 256>>>(pt, ph, b1, n);
    k_bnfix<<<1, 128>>>(g1, be1, invN);

    // layer 2
    k_gemm<128, true><<<ggemm, 256, 128 * 768>>>(ph, W2, pt, nullptr, n);
    k_agg<<<gagg, 256>>>(pt, ph, b2, n);
    k_bnfix<<<1, 128>>>(g2, be2, invN);

    // output projection
    k_out<<<gagg, 256>>>(ph, Wout, bout, out, n);
}

// round 8
// speedup vs baseline: 1.2512x; 1.2512x over previous
#include <cuda_runtime.h>
#include <cuda_bf16.h>

#define MAXN 100000
#define MAXE 1600000
#define TILE 2048

// ---------------- scratch (static device globals; no allocation) ----------------
__device__ __align__(16) float g_t[MAXN * 128];   // post-GEMM features
__device__ __align__(16) float g_h[MAXN * 128];   // post-aggregation features
__device__ float g_dinv[MAXN];
__device__ float g_selfc[MAXN];
__device__ __align__(16) int g_cnt[MAXN];
__device__ int   g_rowp[MAXN + 1];
__device__ int   g_cur[MAXN];
__device__ int   g_col[MAXE];
__device__ float g_w[MAXE];
__device__ int   g_bsum[256];
__device__ int   g_boff[256];
__device__ float g_stats[256];   // [0:128) sum, [128:256) sumsq
__device__ float g_a[128];       // BN fused scale
__device__ float g_c2[128];      // BN fused shift
__device__ float g_sc[128];      // scene_context @ W1[64:128,:]

// ---------------- preprocessing ----------------
__global__ void k_zero(int n) {
    int i = blockIdx.x * blockDim.x + threadIdx.x;
    if (i < n) g_cnt[i] = 0;
    if (i < 256) g_stats[i] = 0.f;
}

__global__ void k_count(const int* __restrict__ dst, int E) {
    int e = blockIdx.x * blockDim.x + threadIdx.x;
    if (e < E) atomicAdd(&g_cnt[dst[e]], 1);
}

// ---- multi-block exclusive scan of g_cnt -> g_rowp/g_cur (+ fused degree calc) ----
// Phase A: per-block tile sums
__global__ void __launch_bounds__(256) k_scanA(int n) {
    __shared__ int wsum[8];
    int blk = blockIdx.x;
    int base = blk * TILE + threadIdx.x * 8;
    int s = 0;
    if (base + 7 < n) {
        int4 a = *(const int4*)&g_cnt[base];
        int4 b = *(const int4*)&g_cnt[base + 4];
        s = a.x + a.y + a.z + a.w + b.x + b.y + b.z + b.w;
    } else {
        for (int j = 0; j < 8; j++)
            if (base + j < n) s += g_cnt[base + j];
    }
    for (int o = 16; o; o >>= 1) s += __shfl_down_sync(0xffffffffu, s, o);
    if ((threadIdx.x & 31) == 0) wsum[threadIdx.x >> 5] = s;
    __syncthreads();
    if (threadIdx.x < 8) {
        int v = wsum[threadIdx.x];
        v += __shfl_down_sync(0xffu, v, 4);
        v += __shfl_down_sync(0xffu, v, 2);
        v += __shfl_down_sync(0xffu, v, 1);
        if (threadIdx.x == 0) g_bsum[blk] = v;
    }
}

// Phase B: single small block scans the block sums (nb <= 256)
__global__ void k_scanB(int nb, int n, int E) {
    __shared__ int sm[256];
    int t = threadIdx.x;
    int v = (t < nb) ? g_bsum[t] : 0;
    sm[t] = v;
    __syncthreads();
    for (int o = 1; o < 256; o <<= 1) {
        int u = (t >= o) ? sm[t - o] : 0;
        __syncthreads();
        sm[t] += u;
        __syncthreads();
    }
    if (t < nb) g_boff[t] = sm[t] - v;  // exclusive
    if (t == 0) g_rowp[n] = E;
}

// Phase C: per-block local scan + global offset; also computes dinv/selfc (fused k_deg)
__global__ void __launch_bounds__(256) k_scanC(int n) {
    __shared__ int woff[8];
    int blk = blockIdx.x;
    int tid = threadIdx.x;
    int lane = tid & 31, wid = tid >> 5;
    int base = blk * TILE + tid * 8;
    int v[8];
    if (base + 7 < n) {
        int4 a = *(const int4*)&g_cnt[base];
        int4 b = *(const int4*)&g_cnt[base + 4];
        v[0] = a.x; v[1] = a.y; v[2] = a.z; v[3] = a.w;
        v[4] = b.x; v[5] = b.y; v[6] = b.z; v[7] = b.w;
    } else {
        for (int j = 0; j < 8; j++) v[j] = (base + j < n) ? g_cnt[base + j] : 0;
    }
    int s = 0;
#pragma unroll
    for (int j = 0; j < 8; j++) s += v[j];
    int inc = s;
    for (int o = 1; o < 32; o <<= 1) {
        int u = __shfl_up_sync(0xffffffffu, inc, o);
        if (lane >= o) inc += u;
    }
    if (lane == 31) woff[wid] = inc;
    __syncthreads();
    if (wid == 0 && lane < 8) {
        int u = woff[lane];
        int iv = u;
        for (int o = 1; o < 8; o <<= 1) {
            int q = __shfl_up_sync(0xffu, iv, o);
            if (lane >= o) iv += q;
        }
        woff[lane] = iv - u;  // exclusive warp offsets
    }
    __syncthreads();
    int run = g_boff[blk] + woff[wid] + (inc - s);
#pragma unroll
    for (int j = 0; j < 8; j++) {
        int i = base + j;
        if (i < n) {
            g_rowp[i] = run;
            g_cur[i] = run;
            float d = 1.f + (float)v[j];
            float r = rsqrtf(d);
            g_dinv[i] = r;
            g_selfc[i] = r * r;
        }
        run += v[j];
    }
}

__global__ void k_scatter(const int* __restrict__ src, const int* __restrict__ dst, int E) {
    int e = blockIdx.x * blockDim.x + threadIdx.x;
    if (e < E) {
        int d = dst[e], s = src[e];
        int p = atomicAdd(&g_cur[d], 1);
        g_col[p] = s;
        g_w[p] = g_dinv[s] * g_dinv[d];
    }
}

// sc[c] = sum_j scene[j] * W1[64+j][c]   (constant row of layer-1 GEMM output)
__global__ void k_prep(const float* __restrict__ scene, const float* __restrict__ W1) {
    int c = threadIdx.x;
    float s = 0.f;
    for (int j = 0; j < 64; j++) s = fmaf(scene[j], W1[(64 + j) * 128 + c], s);
    g_sc[c] = s;
}

// ---------------- GEMM: C[n,128] = op(A[n,K]) @ B[K,128] (+ addrow) ----------------
// op = identity (TR=false) or fused BN+ReLU: relu(a*v + c) (TR=true)
template <int K, bool TR>
__global__ void __launch_bounds__(256) k_gemm(const float* __restrict__ A,
                                              const float* __restrict__ B,
                                              float* __restrict__ C,
                                              const float* __restrict__ addrow,
                                              int n) {
    extern __shared__ float smem[];
    float* Bs = smem;            // K*128
    float* As = smem + K * 128;  // K*64  (transposed: As[k*64 + r])
    int tid = threadIdx.x;
    int row0 = blockIdx.x * 64;

    for (int i = tid; i < K * 32; i += 256)
        ((float4*)Bs)[i] = ((const float4*)B)[i];

    for (int i = tid; i < 64 * (K / 4); i += 256) {
        int r = i / (K / 4);
        int kq = i - r * (K / 4);
        int grow = row0 + r;
        float4 v = make_float4(0.f, 0.f, 0.f, 0.f);
        if (grow < n) v = ((const float4*)A)[grow * (K / 4) + kq];
        int k = kq * 4;
        if (TR) {
            v.x = fmaxf(fmaf(v.x, g_a[k + 0], g_c2[k + 0]), 0.f);
            v.y = fmaxf(fmaf(v.y, g_a[k + 1], g_c2[k + 1]), 0.f);
            v.z = fmaxf(fmaf(v.z, g_a[k + 2], g_c2[k + 2]), 0.f);
            v.w = fmaxf(fmaf(v.w, g_a[k + 3], g_c2[k + 3]), 0.f);
        }
        As[(k + 0) * 64 + r] = v.x;
        As[(k + 1) * 64 + r] = v.y;
        As[(k + 2) * 64 + r] = v.z;
        As[(k + 3) * 64 + r] = v.w;
    }
    __syncthreads();

    int tr = tid >> 4;  // 0..15 -> rows tr*4 .. tr*4+3
    int tc = tid & 15;  // 0..15 -> cols tc*8 .. tc*8+7
    float acc[4][8];
#pragma unroll
    for (int r = 0; r < 4; r++)
#pragma unroll
        for (int c = 0; c < 8; c++) acc[r][c] = 0.f;

#pragma unroll 8
    for (int k = 0; k < K; k++) {
        float4 a = *(const float4*)(As + k * 64 + tr * 4);
        float4 b0 = *(const float4*)(Bs + k * 128 + tc * 8);
        float4 b1 = *(const float4*)(Bs + k * 128 + tc * 8 + 4);
        float av[4] = {a.x, a.y, a.z, a.w};
        float bv[8] = {b0.x, b0.y, b0.z, b0.w, b1.x, b1.y, b1.z, b1.w};
#pragma unroll
        for (int r = 0; r < 4; r++)
#pragma unroll
            for (int c = 0; c < 8; c++)
                acc[r][c] = fmaf(av[r], bv[c], acc[r][c]);
    }

    float add[8];
#pragma unroll
    for (int c = 0; c < 8; c++) add[c] = addrow ? addrow[tc * 8 + c] : 0.f;

#pragma unroll
    for (int r = 0; r < 4; r++) {
        int grow = row0 + tr * 4 + r;
        if (grow < n) {
            float4 o0 = make_float4(acc[r][0] + add[0], acc[r][1] + add[1],
                                    acc[r][2] + add[2], acc[r][3] + add[3]);
            float4 o1 = make_float4(acc[r][4] + add[4], acc[r][5] + add[5],
                                    acc[r][6] + add[6], acc[r][7] + add[7]);
            ((float4*)C)[grow * 32 + tc * 2] = o0;
            ((float4*)C)[grow * 32 + tc * 2 + 1] = o1;
        }
    }
}

// ---------------- aggregation: h[i] = relu(sum_e w*t[col] + selfc[i]*t[i] + b) ----------------
// warp per node, float4 per lane (4 channels). Fuses BN statistics accumulation.
__global__ void __launch_bounds__(256) k_agg(const float* __restrict__ t,
                                             float* __restrict__ h,
                                             const float* __restrict__ bias,
                                             int n) {
    __shared__ float bsum[128];
    __shared__ float bsq[128];
    int tid = threadIdx.x;
    if (tid < 128) { bsum[tid] = 0.f; bsq[tid] = 0.f; }
    __syncthreads();

    int lane = tid & 31;
    int gw = (blockIdx.x * 256 + tid) >> 5;
    int nw = (gridDim.x * 256) >> 5;
    const float4* t4 = (const float4*)t;
    float4 bi = ((const float4*)bias)[lane];
    float sx = 0, sy = 0, sz = 0, sw = 0;
    float qx = 0, qy = 0, qz = 0, qw = 0;

    for (int i = gw; i < n; i += nw) {
        int s = g_rowp[i], e = g_rowp[i + 1];
        float ax = 0, ay = 0, az = 0, aw = 0;
        int ee = s;
        for (; ee + 3 < e; ee += 4) {
            int j0 = g_col[ee], j1 = g_col[ee + 1], j2 = g_col[ee + 2], j3 = g_col[ee + 3];
            float w0 = g_w[ee], w1 = g_w[ee + 1], w2 = g_w[ee + 2], w3 = g_w[ee + 3];
            float4 v0 = t4[j0 * 32 + lane];
            float4 v1 = t4[j1 * 32 + lane];
            float4 v2 = t4[j2 * 32 + lane];
            float4 v3 = t4[j3 * 32 + lane];
            ax = fmaf(w0, v0.x, ax); ay = fmaf(w0, v0.y, ay); az = fmaf(w0, v0.z, az); aw = fmaf(w0, v0.w, aw);
            ax = fmaf(w1, v1.x, ax); ay = fmaf(w1, v1.y, ay); az = fmaf(w1, v1.z, az); aw = fmaf(w1, v1.w, aw);
            ax = fmaf(w2, v2.x, ax); ay = fmaf(w2, v2.y, ay); az = fmaf(w2, v2.z, az); aw = fmaf(w2, v2.w, aw);
            ax = fmaf(w3, v3.x, ax); ay = fmaf(w3, v3.y, ay); az = fmaf(w3, v3.z, az); aw = fmaf(w3, v3.w, aw);
        }
        for (; ee < e; ee++) {
            int j = g_col[ee];
            float w0 = g_w[ee];
            float4 v = t4[j * 32 + lane];
            ax = fmaf(w0, v.x, ax); ay = fmaf(w0, v.y, ay); az = fmaf(w0, v.z, az); aw = fmaf(w0, v.w, aw);
        }
        float sc = g_selfc[i];
        float4 vs = t4[i * 32 + lane];
        float rx = fmaxf(fmaf(sc, vs.x, ax) + bi.x, 0.f);
        float ry = fmaxf(fmaf(sc, vs.y, ay) + bi.y, 0.f);
        float rz = fmaxf(fmaf(sc, vs.z, az) + bi.z, 0.f);
        float rw = fmaxf(fmaf(sc, vs.w, aw) + bi.w, 0.f);
        float4 r = make_float4(rx, ry, rz, rw);
        ((float4*)h)[i * 32 + lane] = r;
        sx += rx; sy += ry; sz += rz; sw += rw;
        qx += rx * rx; qy += ry * ry; qz += rz * rz; qw += rw * rw;
    }

    int c = lane * 4;
    atomicAdd(&bsum[c + 0], sx); atomicAdd(&bsum[c + 1], sy);
    atomicAdd(&bsum[c + 2], sz); atomicAdd(&bsum[c + 3], sw);
    atomicAdd(&bsq[c + 0], qx); atomicAdd(&bsq[c + 1], qy);
    atomicAdd(&bsq[c + 2], qz); atomicAdd(&bsq[c + 3], qw);
    __syncthreads();
    if (tid < 128) {
        atomicAdd(&g_stats[tid], bsum[tid]);
        atomicAdd(&g_stats[128 + tid], bsq[tid]);
    }
}

// ---------------- BN finalize: a = g*rsqrt(var+eps), c2 = be - mu*a; reset stats ----------------
__global__ void k_bnfix(const float* __restrict__ gam, const float* __restrict__ bet, float invN) {
    int c = threadIdx.x;
    float mu = g_stats[c] * invN;
    float var = g_stats[128 + c] * invN - mu * mu;
    float a = gam[c] * rsqrtf(var + 1e-5f);
    g_a[c] = a;
    g_c2[c] = bet[c] - mu * a;
    g_stats[c] = 0.f;
    g_stats[128 + c] = 0.f;
}

// ---------------- output GEMM: out[n,8] = relu(bn(h)) @ Wout + bout ----------------
__global__ void __launch_bounds__(256) k_out(const float* __restrict__ h,
                                             const float* __restrict__ Wout,
                                             const float* __restrict__ bout,
                                             float* __restrict__ out,
                                             int n) {
    int tid = threadIdx.x;
    int lane = tid & 31;
    int gw = (blockIdx.x * 256 + tid) >> 5;
    int nw = (gridDim.x * 256) >> 5;
    const float4* h4 = (const float4*)h;
    int k = lane * 4;
    float a0 = g_a[k], a1 = g_a[k + 1], a2 = g_a[k + 2], a3 = g_a[k + 3];
    float c0 = g_c2[k], c1 = g_c2[k + 1], c2 = g_c2[k + 2], c3 = g_c2[k + 3];
    float wreg[4][8];
#pragma unroll
    for (int j = 0; j < 4; j++)
#pragma unroll
        for (int c = 0; c < 8; c++) wreg[j][c] = Wout[(k + j) * 8 + c];
    float b0 = bout[0], b1 = bout[1], b2 = bout[2], b3 = bout[3];
    float b4 = bout[4], b5 = bout[5], b6 = bout[6], b7 = bout[7];

    for (int i = gw; i < n; i += nw) {
        float4 v = h4[i * 32 + lane];
        float v0 = fmaxf(fmaf(v.x, a0, c0), 0.f);
        float v1 = fmaxf(fmaf(v.y, a1, c1), 0.f);
        float v2 = fmaxf(fmaf(v.z, a2, c2), 0.f);
        float v3 = fmaxf(fmaf(v.w, a3, c3), 0.f);
        float p[8];
#pragma unroll
        for (int c = 0; c < 8; c++) {
            p[c] = fmaf(v0, wreg[0][c],
                   fmaf(v1, wreg[1][c],
                   fmaf(v2, wreg[2][c], v3 * wreg[3][c])));
        }
#pragma unroll
        for (int c = 0; c < 8; c++) {
            p[c] += __shfl_down_sync(0xffffffffu, p[c], 16);
            p[c] += __shfl_down_sync(0xffffffffu, p[c], 8);
            p[c] += __shfl_down_sync(0xffffffffu, p[c], 4);
            p[c] += __shfl_down_sync(0xffffffffu, p[c], 2);
            p[c] += __shfl_down_sync(0xffffffffu, p[c], 1);
        }
        if (lane == 0) {
            float4 o0 = make_float4(p[0] + b0, p[1] + b1, p[2] + b2, p[3] + b3);
            float4 o1 = make_float4(p[4] + b4, p[5] + b5, p[6] + b6, p[7] + b7);
            ((float4*)out)[i * 2] = o0;
            ((float4*)out)[i * 2 + 1] = o1;
        }
    }
}

// ---------------- launch ----------------
extern "C" void kernel_launch(void* const* d_in, const int* in_sizes, int n_in,
                              void* d_out, int out_size) {
    const float* x     = (const float*)d_in[0];
    const int*   src   = (const int*)d_in[1];
    const int*   dst   = (const int*)d_in[2];
    const float* scene = (const float*)d_in[3];
    const float* W1    = (const float*)d_in[4];
    const float* b1    = (const float*)d_in[5];
    const float* g1    = (const float*)d_in[6];
    const float* be1   = (const float*)d_in[7];
    const float* W2    = (const float*)d_in[8];
    const float* b2    = (const float*)d_in[9];
    const float* g2    = (const float*)d_in[10];
    const float* be2   = (const float*)d_in[11];
    const float* Wout  = (const float*)d_in[12];
    const float* bout  = (const float*)d_in[13];
    float* out = (float*)d_out;

    int n = in_sizes[0] / 64;
    int E = in_sizes[1];

    float *pt, *ph, *psc;
    cudaGetSymbolAddress((void**)&pt, g_t);
    cudaGetSymbolAddress((void**)&ph, g_h);
    cudaGetSymbolAddress((void**)&psc, g_sc);

    cudaFuncSetAttribute(k_gemm<64, false>, cudaFuncAttributeMaxDynamicSharedMemorySize, 64 * 768);
    cudaFuncSetAttribute(k_gemm<128, true>, cudaFuncAttributeMaxDynamicSharedMemorySize, 128 * 768);

    int gbn = (n + 255) / 256;
    int gbe = (E + 255) / 256;
    int ggemm = (n + 63) / 64;
    int gagg = 2368;  // 148 SMs * 16 blocks
    int nb = (n + TILE - 1) / TILE;
    float invN = 1.0f / (float)n;

    // graph preprocessing (reused by both layers)
    k_zero<<<gbn, 256>>>(n);
    k_count<<<gbe, 256>>>(dst, E);
    k_scanA<<<nb, 256>>>(n);
    k_scanB<<<1, 256>>>(nb, n, E);
    k_scanC<<<nb, 256>>>(n);          // also computes dinv/selfc
    k_scatter<<<gbe, 256>>>(src, dst, E);
    k_prep<<<1, 128>>>(scene, W1);

    // layer 1
    k_gemm<64, false><<<ggemm, 256, 64 * 768>>>(x, W1, pt, psc, n);
    k_agg<<<gagg, 256>>>(pt, ph, b1, n);
    k_bnfix<<<1, 128>>>(g1, be1, invN);

    // layer 2
    k_gemm<128, true><<<ggemm, 256, 128 * 768>>>(ph, W2, pt, nullptr, n);
    k_agg<<<gagg, 256>>>(pt, ph, b2, n);
    k_bnfix<<<1, 128>>>(g2, be2, invN);

    // output projection
    k_out<<<gagg, 256>>>(ph, Wout, bout, out, n);
}

// round 10
// speedup vs baseline: 1.4714x; 1.1760x over previous
#include <cuda_runtime.h>
#include <cuda_bf16.h>
#include <cstdint>

#define MAXN 100000
#define MAXE 1600000
#define TILE 2048

// ---------------- scratch (static device globals; no allocation) ----------------
__device__ __align__(16) float g_t[MAXN * 128];   // post-GEMM features
__device__ __align__(16) float g_h[MAXN * 128];   // post-aggregation features
__device__ float g_dinv[MAXN];
__device__ float g_selfc[MAXN];
__device__ __align__(16) int g_cnt[MAXN];
__device__ int   g_rowp[MAXN + 1];
__device__ int   g_cur[MAXN];
__device__ int   g_col[MAXE];
__device__ float g_w[MAXE];
__device__ int   g_bsum[256];
__device__ int   g_boff[256];
__device__ float g_stats[256];   // [0:128) sum, [128:256) sumsq
__device__ float g_a[128];       // BN fused scale
__device__ float g_c2[128];      // BN fused shift
__device__ float g_sc[128];      // scene_context @ W1[64:128,:]

// ---------------- preprocessing ----------------
__global__ void k_zero(int n) {
    int i = blockIdx.x * blockDim.x + threadIdx.x;
    if (i < n) g_cnt[i] = 0;
    if (i < 256) g_stats[i] = 0.f;
}

__global__ void k_count(const int* __restrict__ dst, int E) {
    int e = blockIdx.x * blockDim.x + threadIdx.x;
    if (e < E) atomicAdd(&g_cnt[dst[e]], 1);
}

// ---- multi-block exclusive scan of g_cnt -> g_rowp/g_cur (+ fused degree calc) ----
__global__ void __launch_bounds__(256) k_scanA(int n) {
    __shared__ int wsum[8];
    int blk = blockIdx.x;
    int base = blk * TILE + threadIdx.x * 8;
    int s = 0;
    if (base + 7 < n) {
        int4 a = *(const int4*)&g_cnt[base];
        int4 b = *(const int4*)&g_cnt[base + 4];
        s = a.x + a.y + a.z + a.w + b.x + b.y + b.z + b.w;
    } else {
        for (int j = 0; j < 8; j++)
            if (base + j < n) s += g_cnt[base + j];
    }
    for (int o = 16; o; o >>= 1) s += __shfl_down_sync(0xffffffffu, s, o);
    if ((threadIdx.x & 31) == 0) wsum[threadIdx.x >> 5] = s;
    __syncthreads();
    if (threadIdx.x < 8) {
        int v = wsum[threadIdx.x];
        v += __shfl_down_sync(0xffu, v, 4);
        v += __shfl_down_sync(0xffu, v, 2);
        v += __shfl_down_sync(0xffu, v, 1);
        if (threadIdx.x == 0) g_bsum[blk] = v;
    }
}

__global__ void k_scanB(int nb, int n, int E) {
    __shared__ int sm[256];
    int t = threadIdx.x;
    int v = (t < nb) ? g_bsum[t] : 0;
    sm[t] = v;
    __syncthreads();
    for (int o = 1; o < 256; o <<= 1) {
        int u = (t >= o) ? sm[t - o] : 0;
        __syncthreads();
        sm[t] += u;
        __syncthreads();
    }
    if (t < nb) g_boff[t] = sm[t] - v;  // exclusive
    if (t == 0) g_rowp[n] = E;
}

__global__ void __launch_bounds__(256) k_scanC(int n) {
    __shared__ int woff[8];
    int blk = blockIdx.x;
    int tid = threadIdx.x;
    int lane = tid & 31, wid = tid >> 5;
    int base = blk * TILE + tid * 8;
    int v[8];
    if (base + 7 < n) {
        int4 a = *(const int4*)&g_cnt[base];
        int4 b = *(const int4*)&g_cnt[base + 4];
        v[0] = a.x; v[1] = a.y; v[2] = a.z; v[3] = a.w;
        v[4] = b.x; v[5] = b.y; v[6] = b.z; v[7] = b.w;
    } else {
        for (int j = 0; j < 8; j++) v[j] = (base + j < n) ? g_cnt[base + j] : 0;
    }
    int s = 0;
#pragma unroll
    for (int j = 0; j < 8; j++) s += v[j];
    int inc = s;
    for (int o = 1; o < 32; o <<= 1) {
        int u = __shfl_up_sync(0xffffffffu, inc, o);
        if (lane >= o) inc += u;
    }
    if (lane == 31) woff[wid] = inc;
    __syncthreads();
    if (wid == 0 && lane < 8) {
        int u = woff[lane];
        int iv = u;
        for (int o = 1; o < 8; o <<= 1) {
            int q = __shfl_up_sync(0xffu, iv, o);
            if (lane >= o) iv += q;
        }
        woff[lane] = iv - u;  // exclusive warp offsets
    }
    __syncthreads();
    int run = g_boff[blk] + woff[wid] + (inc - s);
#pragma unroll
    for (int j = 0; j < 8; j++) {
        int i = base + j;
        if (i < n) {
            g_rowp[i] = run;
            g_cur[i] = run;
            float d = 1.f + (float)v[j];
            float r = rsqrtf(d);
            g_dinv[i] = r;
            g_selfc[i] = r * r;
        }
        run += v[j];
    }
}

__global__ void k_scatter(const int* __restrict__ src, const int* __restrict__ dst, int E) {
    int e = blockIdx.x * blockDim.x + threadIdx.x;
    if (e < E) {
        int d = dst[e], s = src[e];
        int p = atomicAdd(&g_cur[d], 1);
        g_col[p] = s;
        g_w[p] = g_dinv[s] * g_dinv[d];
    }
}

// sc[c] = sum_j scene[j] * W1[64+j][c]
__global__ void k_prep(const float* __restrict__ scene, const float* __restrict__ W1) {
    int c = threadIdx.x;
    float s = 0.f;
    for (int j = 0; j < 64; j++) s = fmaf(scene[j], W1[(64 + j) * 128 + c], s);
    g_sc[c] = s;
}

// ---------------- TF32 tensor-core GEMM (3xTF32 split for ~fp32 accuracy) ----------
// C[n,128] = op(A[n,K]) @ B[K,128] (+ addrow).  op = BN+ReLU when TR.
// Block: 128 rows x 128 cols, 256 threads (8 warps in 2(m) x 4(n) grid).
// Warp tile: 64x32 -> 4x4 m16n8k8 mma tiles.  K chunked by 64.
// smem holds pre-split hi/lo tf32 copies of A-chunk and B-chunk.

__device__ __forceinline__ void tf32split(float x, uint32_t& hi, uint32_t& lo) {
    uint32_t h;
    asm("cvt.rna.tf32.f32 %0, %1;" : "=r"(h) : "f"(x));
    float hf = __uint_as_float(h);
    uint32_t l;
    asm("cvt.rna.tf32.f32 %0, %1;" : "=r"(l) : "f"(x - hf));
    hi = h; lo = l;
}

__device__ __forceinline__ void mma_tf32(float* c, const uint32_t* a, uint32_t b0, uint32_t b1) {
    asm volatile(
        "mma.sync.aligned.m16n8k8.row.col.f32.tf32.tf32.f32 "
        "{%0,%1,%2,%3}, {%4,%5,%6,%7}, {%8,%9}, {%0,%1,%2,%3};\n"
        : "+f"(c[0]), "+f"(c[1]), "+f"(c[2]), "+f"(c[3])
        : "r"(a[0]), "r"(a[1]), "r"(a[2]), "r"(a[3]), "r"(b0), "r"(b1));
}

#define LDA 68   // 64 + 4 pad: A-frag LDS bank = (4g+t)%32, conflict-free
#define LDB 132  // 128 + 4 pad: B-frag LDS bank = (4t+g)%32, conflict-free
#define GEMM_SMEM ((2 * 128 * LDA + 2 * 64 * LDB) * 4)

template <int K, bool TR>
__global__ void __launch_bounds__(256) k_gemmtc(const float* __restrict__ A,
                                                const float* __restrict__ B,
                                                float* __restrict__ C,
                                                const float* __restrict__ addrow,
                                                int n) {
    extern __shared__ uint32_t sm[];
    uint32_t* Ahi = sm;                       // [128][LDA]
    uint32_t* Alo = sm + 128 * LDA;
    uint32_t* Bhi = sm + 2 * 128 * LDA;       // [64][LDB]
    uint32_t* Blo = Bhi + 64 * LDB;

    int tid = threadIdx.x;
    int lane = tid & 31;
    int wid = tid >> 5;
    int g = lane >> 2;    // groupID 0..7
    int t = lane & 3;     // threadID_in_group 0..3
    int wm = wid & 1;     // warp m index (0..1)
    int wn = wid >> 1;    // warp n index (0..3)
    int r0w = wm * 64;    // warp row offset in block tile
    int n0w = wn * 32;    // warp col offset

    int row0 = blockIdx.x * 128;

    float acc[4][4][4];
#pragma unroll
    for (int mt = 0; mt < 4; mt++)
#pragma unroll
        for (int nt = 0; nt < 4; nt++)
#pragma unroll
            for (int r = 0; r < 4; r++) acc[mt][nt][r] = 0.f;

    const int NCHUNK = K / 64;
    for (int kc = 0; kc < NCHUNK; kc++) {
        // ---- stage A chunk [128 rows][64 cols] with split (and optional BN+ReLU) ----
        for (int i = tid; i < 128 * 16; i += 256) {
            int r = i >> 4;          // row in tile
            int q = i & 15;          // float4 col in chunk
            int grow = row0 + r;
            float4 v = make_float4(0.f, 0.f, 0.f, 0.f);
            if (grow < n) v = ((const float4*)A)[grow * (K / 4) + kc * 16 + q];
            float vv[4] = {v.x, v.y, v.z, v.w};
#pragma unroll
            for (int j = 0; j < 4; j++) {
                int col = q * 4 + j;             // col within chunk
                float x = vv[j];
                if (TR) {
                    int gc = kc * 64 + col;
                    x = fmaxf(fmaf(x, g_a[gc], g_c2[gc]), 0.f);
                }
                uint32_t hi, lo;
                tf32split(x, hi, lo);
                Ahi[r * LDA + col] = hi;
                Alo[r * LDA + col] = lo;
            }
        }
        // ---- stage B chunk [64 rows][128 cols] with split ----
        for (int i = tid; i < 64 * 32; i += 256) {
            int r = i >> 5;          // row within chunk
            int q = i & 31;          // float4 col
            float4 v = ((const float4*)B)[(kc * 64 + r) * 32 + q];
            float vv[4] = {v.x, v.y, v.z, v.w};
#pragma unroll
            for (int j = 0; j < 4; j++) {
                uint32_t hi, lo;
                tf32split(vv[j], hi, lo);
                Bhi[r * LDB + q * 4 + j] = hi;
                Blo[r * LDB + q * 4 + j] = lo;
            }
        }
        __syncthreads();

        // ---- mainloop over k8 steps ----
#pragma unroll 4
        for (int kk = 0; kk < 64; kk += 8) {
            uint32_t ahi[4][4], alo[4][4];
#pragma unroll
            for (int mt = 0; mt < 4; mt++) {
                int rb = r0w + mt * 16;
                ahi[mt][0] = Ahi[(rb + g) * LDA + kk + t];
                ahi[mt][1] = Ahi[(rb + g + 8) * LDA + kk + t];
                ahi[mt][2] = Ahi[(rb + g) * LDA + kk + t + 4];
                ahi[mt][3] = Ahi[(rb + g + 8) * LDA + kk + t + 4];
                alo[mt][0] = Alo[(rb + g) * LDA + kk + t];
                alo[mt][1] = Alo[(rb + g + 8) * LDA + kk + t];
                alo[mt][2] = Alo[(rb + g) * LDA + kk + t + 4];
                alo[mt][3] = Alo[(rb + g + 8) * LDA + kk + t + 4];
            }
#pragma unroll
            for (int nt = 0; nt < 4; nt++) {
                int nb = n0w + nt * 8 + g;
                uint32_t b0h = Bhi[(kk + t) * LDB + nb];
                uint32_t b1h = Bhi[(kk + t + 4) * LDB + nb];
                uint32_t b0l = Blo[(kk + t) * LDB + nb];
                uint32_t b1l = Blo[(kk + t + 4) * LDB + nb];
#pragma unroll
                for (int mt = 0; mt < 4; mt++) {
                    mma_tf32(acc[mt][nt], ahi[mt], b0h, b1h);   // hi*hi
                    mma_tf32(acc[mt][nt], ahi[mt], b0l, b1l);   // hi*lo
                    mma_tf32(acc[mt][nt], alo[mt], b0h, b1h);   // lo*hi
                }
            }
        }
        __syncthreads();
    }

    // ---- epilogue: C[row][col] (+ addrow) ----
#pragma unroll
    for (int nt = 0; nt < 4; nt++) {
        int col = n0w + nt * 8 + 2 * t;
        float add0 = addrow ? addrow[col] : 0.f;
        float add1 = addrow ? addrow[col + 1] : 0.f;
#pragma unroll
        for (int mt = 0; mt < 4; mt++) {
            int row1 = row0 + r0w + mt * 16 + g;
            int row2 = row1 + 8;
            if (row1 < n)
                *(float2*)&C[row1 * 128 + col] =
                    make_float2(acc[mt][nt][0] + add0, acc[mt][nt][1] + add1);
            if (row2 < n)
                *(float2*)&C[row2 * 128 + col] =
                    make_float2(acc[mt][nt][2] + add0, acc[mt][nt][3] + add1);
        }
    }
}

// ---------------- aggregation: h[i] = relu(sum_e w*t[col] + selfc[i]*t[i] + b) ----------------
__global__ void __launch_bounds__(256) k_agg(const float* __restrict__ t,
                                             float* __restrict__ h,
                                             const float* __restrict__ bias,
                                             int n) {
    __shared__ float bsum[128];
    __shared__ float bsq[128];
    int tid = threadIdx.x;
    if (tid < 128) { bsum[tid] = 0.f; bsq[tid] = 0.f; }
    __syncthreads();

    int lane = tid & 31;
    int gw = (blockIdx.x * 256 + tid) >> 5;
    int nw = (gridDim.x * 256) >> 5;
    const float4* t4 = (const float4*)t;
    float4 bi = ((const float4*)bias)[lane];
    float sx = 0, sy = 0, sz = 0, sw = 0;
    float qx = 0, qy = 0, qz = 0, qw = 0;

    for (int i = gw; i < n; i += nw) {
        int s = g_rowp[i], e = g_rowp[i + 1];
        float ax = 0, ay = 0, az = 0, aw = 0;
        int ee = s;
        for (; ee + 3 < e; ee += 4) {
            int j0 = g_col[ee], j1 = g_col[ee + 1], j2 = g_col[ee + 2], j3 = g_col[ee + 3];
            float w0 = g_w[ee], w1 = g_w[ee + 1], w2 = g_w[ee + 2], w3 = g_w[ee + 3];
            float4 v0 = t4[j0 * 32 + lane];
            float4 v1 = t4[j1 * 32 + lane];
            float4 v2 = t4[j2 * 32 + lane];
            float4 v3 = t4[j3 * 32 + lane];
            ax = fmaf(w0, v0.x, ax); ay = fmaf(w0, v0.y, ay); az = fmaf(w0, v0.z, az); aw = fmaf(w0, v0.w, aw);
            ax = fmaf(w1, v1.x, ax); ay = fmaf(w1, v1.y, ay); az = fmaf(w1, v1.z, az); aw = fmaf(w1, v1.w, aw);
            ax = fmaf(w2, v2.x, ax); ay = fmaf(w2, v2.y, ay); az = fmaf(w2, v2.z, az); aw = fmaf(w2, v2.w, aw);
            ax = fmaf(w3, v3.x, ax); ay = fmaf(w3, v3.y, ay); az = fmaf(w3, v3.z, az); aw = fmaf(w3, v3.w, aw);
        }
        for (; ee < e; ee++) {
            int j = g_col[ee];
            float w0 = g_w[ee];
            float4 v = t4[j * 32 + lane];
            ax = fmaf(w0, v.x, ax); ay = fmaf(w0, v.y, ay); az = fmaf(w0, v.z, az); aw = fmaf(w0, v.w, aw);
        }
        float sc = g_selfc[i];
        float4 vs = t4[i * 32 + lane];
        float rx = fmaxf(fmaf(sc, vs.x, ax) + bi.x, 0.f);
        float ry = fmaxf(fmaf(sc, vs.y, ay) + bi.y, 0.f);
        float rz = fmaxf(fmaf(sc, vs.z, az) + bi.z, 0.f);
        float rw = fmaxf(fmaf(sc, vs.w, aw) + bi.w, 0.f);
        float4 r = make_float4(rx, ry, rz, rw);
        ((float4*)h)[i * 32 + lane] = r;
        sx += rx; sy += ry; sz += rz; sw += rw;
        qx += rx * rx; qy += ry * ry; qz += rz * rz; qw += rw * rw;
    }

    int c = lane * 4;
    atomicAdd(&bsum[c + 0], sx); atomicAdd(&bsum[c + 1], sy);
    atomicAdd(&bsum[c + 2], sz); atomicAdd(&bsum[c + 3], sw);
    atomicAdd(&bsq[c + 0], qx); atomicAdd(&bsq[c + 1], qy);
    atomicAdd(&bsq[c + 2], qz); atomicAdd(&bsq[c + 3], qw);
    __syncthreads();
    if (tid < 128) {
        atomicAdd(&g_stats[tid], bsum[tid]);
        atomicAdd(&g_stats[128 + tid], bsq[tid]);
    }
}

// ---------------- BN finalize ----------------
__global__ void k_bnfix(const float* __restrict__ gam, const float* __restrict__ bet, float invN) {
    int c = threadIdx.x;
    float mu = g_stats[c] * invN;
    float var = g_stats[128 + c] * invN - mu * mu;
    float a = gam[c] * rsqrtf(var + 1e-5f);
    g_a[c] = a;
    g_c2[c] = bet[c] - mu * a;
    g_stats[c] = 0.f;
    g_stats[128 + c] = 0.f;
}

// ---------------- output GEMM: out[n,8] = relu(bn(h)) @ Wout + bout ----------------
__global__ void __launch_bounds__(256) k_out(const float* __restrict__ h,
                                             const float* __restrict__ Wout,
                                             const float* __restrict__ bout,
                                             float* __restrict__ out,
                                             int n) {
    int tid = threadIdx.x;
    int lane = tid & 31;
    int gw = (blockIdx.x * 256 + tid) >> 5;
    int nw = (gridDim.x * 256) >> 5;
    const float4* h4 = (const float4*)h;
    int k = lane * 4;
    float a0 = g_a[k], a1 = g_a[k + 1], a2 = g_a[k + 2], a3 = g_a[k + 3];
    float c0 = g_c2[k], c1 = g_c2[k + 1], c2 = g_c2[k + 2], c3 = g_c2[k + 3];
    float wreg[4][8];
#pragma unroll
    for (int j = 0; j < 4; j++)
#pragma unroll
        for (int c = 0; c < 8; c++) wreg[j][c] = Wout[(k + j) * 8 + c];
    float b0 = bout[0], b1 = bout[1], b2 = bout[2], b3 = bout[3];
    float b4 = bout[4], b5 = bout[5], b6 = bout[6], b7 = bout[7];

    for (int i = gw; i < n; i += nw) {
        float4 v = h4[i * 32 + lane];
        float v0 = fmaxf(fmaf(v.x, a0, c0), 0.f);
        float v1 = fmaxf(fmaf(v.y, a1, c1), 0.f);
        float v2 = fmaxf(fmaf(v.z, a2, c2), 0.f);
        float v3 = fmaxf(fmaf(v.w, a3, c3), 0.f);
        float p[8];
#pragma unroll
        for (int c = 0; c < 8; c++) {
            p[c] = fmaf(v0, wreg[0][c],
                   fmaf(v1, wreg[1][c],
                   fmaf(v2, wreg[2][c], v3 * wreg[3][c])));
        }
#pragma unroll
        for (int c = 0; c < 8; c++) {
            p[c] += __shfl_down_sync(0xffffffffu, p[c], 16);
            p[c] += __shfl_down_sync(0xffffffffu, p[c], 8);
            p[c] += __shfl_down_sync(0xffffffffu, p[c], 4);
            p[c] += __shfl_down_sync(0xffffffffu, p[c], 2);
            p[c] += __shfl_down_sync(0xffffffffu, p[c], 1);
        }
        if (lane == 0) {
            float4 o0 = make_float4(p[0] + b0, p[1] + b1, p[2] + b2, p[3] + b3);
            float4 o1 = make_float4(p[4] + b4, p[5] + b5, p[6] + b6, p[7] + b7);
            ((float4*)out)[i * 2] = o0;
            ((float4*)out)[i * 2 + 1] = o1;
        }
    }
}

// ---------------- launch ----------------
extern "C" void kernel_launch(void* const* d_in, const int* in_sizes, int n_in,
                              void* d_out, int out_size) {
    const float* x     = (const float*)d_in[0];
    const int*   src   = (const int*)d_in[1];
    const int*   dst   = (const int*)d_in[2];
    const float* scene = (const float*)d_in[3];
    const float* W1    = (const float*)d_in[4];
    const float* b1    = (const float*)d_in[5];
    const float* g1    = (const float*)d_in[6];
    const float* be1   = (const float*)d_in[7];
    const float* W2    = (const float*)d_in[8];
    const float* b2    = (const float*)d_in[9];
    const float* g2    = (const float*)d_in[10];
    const float* be2   = (const float*)d_in[11];
    const float* Wout  = (const float*)d_in[12];
    const float* bout  = (const float*)d_in[13];
    float* out = (float*)d_out;

    int n = in_sizes[0] / 64;
    int E = in_sizes[1];

    float *pt, *ph, *psc;
    cudaGetSymbolAddress((void**)&pt, g_t);
    cudaGetSymbolAddress((void**)&ph, g_h);
    cudaGetSymbolAddress((void**)&psc, g_sc);

    cudaFuncSetAttribute(k_gemmtc<64, false>, cudaFuncAttributeMaxDynamicSharedMemorySize, GEMM_SMEM);
    cudaFuncSetAttribute(k_gemmtc<128, true>, cudaFuncAttributeMaxDynamicSharedMemorySize, GEMM_SMEM);

    int gbn = (n + 255) / 256;
    int gbe = (E + 255) / 256;
    int gtc = (n + 127) / 128;
    int gagg = 2368;  // 148 SMs * 16 blocks
    int nb = (n + TILE - 1) / TILE;
    float invN = 1.0f / (float)n;

    // graph preprocessing (reused by both layers)
    k_zero<<<gbn, 256>>>(n);
    k_count<<<gbe, 256>>>(dst, E);
    k_scanA<<<nb, 256>>>(n);
    k_scanB<<<1, 256>>>(nb, n, E);
    k_scanC<<<nb, 256>>>(n);          // also computes dinv/selfc
    k_scatter<<<gbe, 256>>>(src, dst, E);
    k_prep<<<1, 128>>>(scene, W1);

    // layer 1
    k_gemmtc<64, false><<<gtc, 256, GEMM_SMEM>>>(x, W1, pt, psc, n);
    k_agg<<<gagg, 256>>>(pt, ph, b1, n);
    k_bnfix<<<1, 128>>>(g1, be1, invN);

    // layer 2
    k_gemmtc<128, true><<<gtc, 256, GEMM_SMEM>>>(ph, W2, pt, nullptr, n);
    k_agg<<<gagg, 256>>>(pt, ph, b2, n);
    k_bnfix<<<1, 128>>>(g2, be2, invN);

    // output projection
    k_out<<<gagg, 256>>>(ph, Wout, bout, out, n);
}